// round 2
// baseline (speedup 1.0000x reference)
#include <cuda_runtime.h>
#include <cstdint>

// ----------------------------------------------------------------------------
// TuckerLinear on GB300 (sm_103a)
//   out = ((x[:,input_perm] @ W.T)[:,output_inv_perm]) * alpha * pds + bias
//   W = einsum(core[8^6], fo0,fo1,fo2,fi0,fi1,fi2 [16x8])
// Strategy: never materialize W. Mode-wise contractions + 512x512 core GEMM.
// All math fp32; token PAIRS packed into f32x2 (fma.rn.f32x2) for 2x density.
// ----------------------------------------------------------------------------

typedef unsigned long long ull_t;

__device__ __forceinline__ ull_t dup_f32x2(float v) {
    ull_t r; unsigned int b = __float_as_uint(v);
    asm("mov.b64 %0, {%1, %1};" : "=l"(r) : "r"(b));
    return r;
}
__device__ __forceinline__ ull_t pack_f32x2(float a, float b) {
    ull_t r;
    asm("mov.b64 %0, {%1, %2};" : "=l"(r)
        : "r"(__float_as_uint(a)), "r"(__float_as_uint(b)));
    return r;
}
__device__ __forceinline__ float2 unpack_f32x2(ull_t v) {
    unsigned int lo, hi;
    asm("mov.b64 {%0, %1}, %2;" : "=r"(lo), "=r"(hi) : "l"(v));
    return make_float2(__uint_as_float(lo), __uint_as_float(hi));
}
__device__ __forceinline__ ull_t fma_f32x2(ull_t a, ull_t b, ull_t c) {
    ull_t d;
    asm("fma.rn.f32x2 %0, %1, %2, %3;" : "=l"(d) : "l"(a), "l"(b), "l"(c));
    return d;
}

// Scratch: packed Y (token pairs), max 8192 tokens -> 4096 pairs x 512 cols.
__device__ ull_t g_Y2[4096 * 512];

// ============================================================================
// Kernel 1: gather + input-side mode contractions.
// One CTA = one token PAIR. 256 threads.
//   y[d,e,f] = sum_{D,E,F} fi0[D,d] fi1[E,e] fi2[F,f] * x[t, perm[D*256+E*16+F]]
// ============================================================================
#define K1_SMEM_ULL (4096 + 8*257 + 1024 + 3*128)
#define K1_SMEM_BYTES (K1_SMEM_ULL * 8)

__global__ void __launch_bounds__(256) k_input(
    const float* __restrict__ x, const int* __restrict__ iperm,
    const float* __restrict__ fi0, const float* __restrict__ fi1,
    const float* __restrict__ fi2)
{
    extern __shared__ char smem_raw[];
    ull_t* xs2  = (ull_t*)smem_raw;          // [4096] packed (tok0, tok1)
    ull_t* t1   = xs2 + 4096;                // [f][de] padded row 257
    ull_t* t2   = t1 + 8 * 257;              // [D*64 + e*8 + f]
    ull_t* fi0d = t2 + 1024;                 // [128] duplicated
    ull_t* fi1d = fi0d + 128;
    ull_t* fi2d = fi1d + 128;

    const int tid = threadIdx.x;
    const int pairIdx = blockIdx.x;

    // Load 2 token rows (coalesced float4), pack into f32x2.
    const float4* r0 = (const float4*)(x + (size_t)pairIdx * 2 * 4096);
    const float4* r1 = r0 + 1024;
    for (int i = tid; i < 1024; i += 256) {
        float4 a = r0[i], b = r1[i];
        xs2[4*i + 0] = pack_f32x2(a.x, b.x);
        xs2[4*i + 1] = pack_f32x2(a.y, b.y);
        xs2[4*i + 2] = pack_f32x2(a.z, b.z);
        xs2[4*i + 3] = pack_f32x2(a.w, b.w);
    }
    if (tid < 128) {
        fi0d[tid] = dup_f32x2(fi0[tid]);
        fi1d[tid] = dup_f32x2(fi1[tid]);
        fi2d[tid] = dup_f32x2(fi2[tid]);
    }
    __syncthreads();

    // Stage A: contract F.  t1[f][de] = sum_F xf[de*16+F] * fi2[F,f]
    {
        const int de = tid;
        // perm indices: 16 consecutive ints -> 4 x int4 (16B aligned).
        const int4* ip4 = (const int4*)(iperm + de*16);
        int pidx[16];
        #pragma unroll
        for (int k = 0; k < 4; k++) {
            int4 v = ip4[k];
            pidx[4*k+0] = v.x; pidx[4*k+1] = v.y;
            pidx[4*k+2] = v.z; pidx[4*k+3] = v.w;
        }
        ull_t xf[16];
        #pragma unroll
        for (int F = 0; F < 16; F++) xf[F] = xs2[pidx[F]];
        ull_t acc[8];
        #pragma unroll
        for (int f = 0; f < 8; f++) acc[f] = 0ull;
        #pragma unroll
        for (int F = 0; F < 16; F++) {
            ull_t xv = xf[F];
            #pragma unroll
            for (int f = 0; f < 8; f++)
                acc[f] = fma_f32x2(xv, fi2d[F*8 + f], acc[f]);
        }
        #pragma unroll
        for (int f = 0; f < 8; f++) t1[f*257 + de] = acc[f];
    }
    __syncthreads();

    // Stage B: contract E.  t2[D*64+e*8+f] = sum_E t1[f][D*16+E] * fi1[E,e]
    #pragma unroll
    for (int k = 0; k < 4; k++) {
        int idx = tid + k*256;
        int D = idx >> 6, e = (idx >> 3) & 7, f = idx & 7;
        ull_t acc = 0ull;
        #pragma unroll
        for (int E = 0; E < 16; E++)
            acc = fma_f32x2(t1[f*257 + D*16 + E], fi1d[E*8 + e], acc);
        t2[idx] = acc;
    }
    __syncthreads();

    // Stage C: contract D.  y[d*64+ef] = sum_D t2[D*64+ef] * fi0[D,d]
    ull_t* yout = &g_Y2[(size_t)pairIdx * 512];
    #pragma unroll
    for (int k = 0; k < 2; k++) {
        int idx = tid + k*256;
        int d = idx >> 6, ef = idx & 63;
        ull_t acc = 0ull;
        #pragma unroll
        for (int D = 0; D < 16; D++)
            acc = fma_f32x2(t2[D*64 + ef], fi0d[D*8 + d], acc);
        yout[idx] = acc;
    }
}

// ============================================================================
// Kernel 2: core GEMM (Z = Y @ core2^T) + output expansion + permuted scatter.
// One CTA = 32 tokens (16 pairs). 256 threads, 1 CTA/SM (big smem).
//   core2[o][h] = core_flat[o*512 + h]   (pure reshape of core[8^6])
// Thread tiling: og = tid&63, pg = tid>>6.  o = og + 64*j (j<8),
// pairs p = pg*4 + q (q<4)  -> 32 packed accumulators/thread.
// Core k-blocks (512x16) register-prefetched + double-buffered in smem
// (pad-17 rows: conflict-free compute reads; scalar STS avoids alignment).
// ============================================================================
#define CORE_TILE_FLOATS (512 * 17)                  // 16 cols + 1 pad
#define K2_YS_BYTES      (512 * 17 * 8)              // Ys padded (69632 B)
#define K2_SMEM_BYTES    (K2_YS_BYTES + 2*CORE_TILE_FLOATS*4 + \
                          (1024 + 2048 + 3*128)*8 + 3*4096*4)

__global__ void __launch_bounds__(256, 1) k_core(
    const float* __restrict__ core,
    const float* __restrict__ fo0, const float* __restrict__ fo1,
    const float* __restrict__ fo2,
    const float* __restrict__ bias, const float* __restrict__ alpha,
    const float* __restrict__ pds, const int* __restrict__ oinv,
    float* __restrict__ out)
{
    extern __shared__ char smem_raw[];
    ull_t* YZ     = (ull_t*)smem_raw;                          // Ys then Zs
    float* cbuf0  = (float*)(smem_raw + K2_YS_BYTES);
    float* cbuf1  = cbuf0 + CORE_TILE_FLOATS;
    ull_t* e1     = (ull_t*)(cbuf1 + CORE_TILE_FLOATS);        // [1024]
    ull_t* e2     = e1 + 1024;                                 // [2048]
    ull_t* fo0d   = e2 + 2048;
    ull_t* fo1d   = fo0d + 128;
    ull_t* fo2d   = fo1d + 128;
    int*   s_oip  = (int*)(fo2d + 128);                        // [4096]
    float* s_pds  = (float*)(s_oip + 4096);                    // [4096] (*alpha)
    float* s_bias = s_pds + 4096;                              // [4096]

    const int tid  = threadIdx.x;
    const int tile = blockIdx.x;

    // Each thread owns 32 floats of a 512x16 core k-block: rows o (idx>>2),
    // 4-float chunk q (idx&3). Global side is 16B aligned -> LDG.128.
    const int c_o = 0; (void)c_o;

    // Prologue: fetch core k-block 0 into regs, store to cbuf0.
    float4 nxt[8];
    #pragma unroll
    for (int k = 0; k < 8; k++) {
        int idx = tid + k*256;
        int o = idx >> 2, q = idx & 3;
        nxt[k] = *(const float4*)(core + (size_t)o*512 + q*4);
    }
    #pragma unroll
    for (int k = 0; k < 8; k++) {
        int idx = tid + k*256;
        int o = idx >> 2, q = idx & 3;
        float* dst = cbuf0 + o*17 + q*4;
        dst[0] = nxt[k].x; dst[1] = nxt[k].y;
        dst[2] = nxt[k].z; dst[3] = nxt[k].w;
    }

    // Load Y tile into smem: Ys[h*17 + pair], coalesced along h.
    const ull_t* ysrc = &g_Y2[(size_t)tile * 16 * 512];
    for (int i = tid; i < 8192; i += 256) {
        int pair = i >> 9, h = i & 511;
        YZ[h*17 + pair] = ysrc[(size_t)pair*512 + h];
    }
    // Epilogue tables.
    float alphaV = alpha[0];
    for (int i = tid; i < 4096; i += 256) {
        s_oip[i]  = oinv[i];
        s_pds[i]  = pds[i] * alphaV;
        s_bias[i] = bias[i];
    }
    if (tid < 128) {
        fo0d[tid] = dup_f32x2(fo0[tid]);
        fo1d[tid] = dup_f32x2(fo1[tid]);
        fo2d[tid] = dup_f32x2(fo2[tid]);
    }
    __syncthreads();

    const int og = tid & 63;
    const int pg = tid >> 6;

    ull_t acc[8][4];
    #pragma unroll
    for (int j = 0; j < 8; j++)
        #pragma unroll
        for (int q = 0; q < 4; q++) acc[j][q] = 0ull;

    // Main GEMM loop over 32 h-blocks of 16; register-prefetch next block.
    for (int kb = 0; kb < 32; kb++) {
        if (kb < 31) {
            #pragma unroll
            for (int k = 0; k < 8; k++) {
                int idx = tid + k*256;
                int o = idx >> 2, q = idx & 3;
                nxt[k] = *(const float4*)(core + (size_t)o*512 + (kb+1)*16 + q*4);
            }
        }

        const float* cb = (kb & 1) ? cbuf1 : cbuf0;
        for (int hh = 0; hh < 16; hh++) {
            const ull_t* yrow = &YZ[(kb*16 + hh)*17 + pg*4];
            ull_t ya0 = yrow[0], ya1 = yrow[1], ya2 = yrow[2], ya3 = yrow[3];
            #pragma unroll
            for (int j = 0; j < 8; j++) {
                ull_t c2 = dup_f32x2(cb[(og + 64*j)*17 + hh]);
                acc[j][0] = fma_f32x2(ya0, c2, acc[j][0]);
                acc[j][1] = fma_f32x2(ya1, c2, acc[j][1]);
                acc[j][2] = fma_f32x2(ya2, c2, acc[j][2]);
                acc[j][3] = fma_f32x2(ya3, c2, acc[j][3]);
            }
        }

        if (kb < 31) {
            float* nbuf = (kb & 1) ? cbuf0 : cbuf1;
            #pragma unroll
            for (int k = 0; k < 8; k++) {
                int idx = tid + k*256;
                int o = idx >> 2, q = idx & 3;
                float* dst = nbuf + o*17 + q*4;
                dst[0] = nxt[k].x; dst[1] = nxt[k].y;
                dst[2] = nxt[k].z; dst[3] = nxt[k].w;
            }
        }
        __syncthreads();
    }

    // Spill Z into smem (overwrites Ys region): Zs[pair*512 + o].
    #pragma unroll
    for (int j = 0; j < 8; j++)
        #pragma unroll
        for (int q = 0; q < 4; q++)
            YZ[(size_t)(pg*4 + q)*512 + og + 64*j] = acc[j][q];
    __syncthreads();

    // Output expansion + permuted scatter, per token pair.
    float* outBase = out + (size_t)tile * 32 * 4096;
    for (int p = 0; p < 16; p++) {
        // Stage 1: contract c.  e1[a*128+b*16+C] = sum_c Z[a*64+b*8+c]*fo2[C,c]
        #pragma unroll
        for (int k = 0; k < 4; k++) {
            int idx = tid + k*256;
            int a_ = idx >> 7, b_ = (idx >> 4) & 7, C_ = idx & 15;
            ull_t a1 = 0ull;
            #pragma unroll
            for (int c_ = 0; c_ < 8; c_++)
                a1 = fma_f32x2(YZ[p*512 + a_*64 + b_*8 + c_], fo2d[C_*8 + c_], a1);
            e1[idx] = a1;
        }
        __syncthreads();
        // Stage 2: contract b.  e2[a*256+B*16+C] = sum_b e1[a*128+b*16+C]*fo1[B,b]
        #pragma unroll
        for (int k = 0; k < 8; k++) {
            int idx = tid + k*256;
            int a_ = idx >> 8, B_ = (idx >> 4) & 15, C_ = idx & 15;
            ull_t a2 = 0ull;
            #pragma unroll
            for (int b_ = 0; b_ < 8; b_++)
                a2 = fma_f32x2(e1[a_*128 + b_*16 + C_], fo1d[B_*8 + b_], a2);
            e2[idx] = a2;
        }
        __syncthreads();
        // Stage 3: contract a + inverse-perm gather + scale/bias + store.
        float* o0 = outBase + (size_t)(2*p) * 4096;
        float* o1 = o0 + 4096;
        #pragma unroll
        for (int k = 0; k < 16; k++) {
            int j = tid + k*256;
            int o = s_oip[j];
            int A_ = o >> 8, bc = o & 255;
            ull_t a3 = 0ull;
            #pragma unroll
            for (int a_ = 0; a_ < 8; a_++)
                a3 = fma_f32x2(e2[a_*256 + bc], fo0d[A_*8 + a_], a3);
            float2 v = unpack_f32x2(a3);
            float s = s_pds[j], bb = s_bias[j];
            o0[j] = v.x * s + bb;
            o1[j] = v.y * s + bb;
        }
        __syncthreads();
    }
}

// ============================================================================
// Launch
// ============================================================================
extern "C" void kernel_launch(void* const* d_in, const int* in_sizes, int n_in,
                              void* d_out, int out_size)
{
    const float* x     = (const float*)d_in[0];
    const float* core  = (const float*)d_in[1];
    const float* fo0   = (const float*)d_in[2];
    const float* fo1   = (const float*)d_in[3];
    const float* fo2   = (const float*)d_in[4];
    const float* fi0   = (const float*)d_in[5];
    const float* fi1   = (const float*)d_in[6];
    const float* fi2   = (const float*)d_in[7];
    const float* bias  = (const float*)d_in[8];
    const float* alpha = (const float*)d_in[9];
    const float* pds   = (const float*)d_in[10];
    const int*   iperm = (const int*)d_in[11];
    const int*   oinv  = (const int*)d_in[12];
    float* out = (float*)d_out;

    int NT = in_sizes[0] / 4096;      // tokens (8192)
    int nPairs = NT / 2;              // 4096
    int nTiles = NT / 32;             // 256

    cudaFuncSetAttribute(k_input, cudaFuncAttributeMaxDynamicSharedMemorySize,
                         K1_SMEM_BYTES);
    cudaFuncSetAttribute(k_core, cudaFuncAttributeMaxDynamicSharedMemorySize,
                         K2_SMEM_BYTES);

    k_input<<<nPairs, 256, K1_SMEM_BYTES>>>(x, iperm, fi0, fi1, fi2);
    k_core<<<nTiles, 256, K2_SMEM_BYTES>>>(core, fo0, fo1, fo2,
                                           bias, alpha, pds, oinv, out);
}

// round 3
// speedup vs baseline: 1.0176x; 1.0176x over previous
#include <cuda_runtime.h>
#include <cstdint>

// ----------------------------------------------------------------------------
// TuckerLinear on GB300 (sm_103a) — 3-kernel pipeline, f32x2 packed token pairs
//   k_input : gather(x, perm) + 3 input-mode contractions  -> g_Y2
//   k_gemm  : Z = Y @ core(512x512)^T                      -> g_Z2
//   k_output: 3 output-mode contractions + inv-perm + scale/bias -> out
// ----------------------------------------------------------------------------

typedef unsigned long long ull_t;

__device__ __forceinline__ ull_t dup_f32x2(float v) {
    ull_t r; unsigned int b = __float_as_uint(v);
    asm("mov.b64 %0, {%1, %1};" : "=l"(r) : "r"(b));
    return r;
}
__device__ __forceinline__ ull_t pack_f32x2(float a, float b) {
    ull_t r;
    asm("mov.b64 %0, {%1, %2};" : "=l"(r)
        : "r"(__float_as_uint(a)), "r"(__float_as_uint(b)));
    return r;
}
__device__ __forceinline__ float2 unpack_f32x2(ull_t v) {
    unsigned int lo, hi;
    asm("mov.b64 {%0, %1}, %2;" : "=r"(lo), "=r"(hi) : "l"(v));
    return make_float2(__uint_as_float(lo), __uint_as_float(hi));
}
__device__ __forceinline__ ull_t fma_f32x2(ull_t a, ull_t b, ull_t c) {
    ull_t d;
    asm("fma.rn.f32x2 %0, %1, %2, %3;" : "=l"(d) : "l"(a), "l"(b), "l"(c));
    return d;
}

// Scratch (packed token pairs): 4096 pairs x 512 cols each.
__device__ ull_t g_Y2[4096 * 512];
__device__ ull_t g_Z2[4096 * 512];

// ============================================================================
// Kernel 1: gather + input-side contractions. One CTA = one token pair.
// smem: xs2[4096] (t2 aliases its head), t1[8*257], fi tables. 52.3KB dynamic.
// ============================================================================
#define K1_SMEM_ULL (4096 + 8*257 + 3*128)
#define K1_SMEM_BYTES (K1_SMEM_ULL * 8)

__global__ void __launch_bounds__(256) k_input(
    const float* __restrict__ x, const int* __restrict__ iperm,
    const float* __restrict__ fi0, const float* __restrict__ fi1,
    const float* __restrict__ fi2)
{
    extern __shared__ char smem_raw[];
    ull_t* xs2  = (ull_t*)smem_raw;          // [4096]; t2 aliases xs2[0..1023]
    ull_t* t2   = xs2;
    ull_t* t1   = xs2 + 4096;                // [f][de] padded row 257
    ull_t* fi0d = t1 + 8 * 257;
    ull_t* fi1d = fi0d + 128;
    ull_t* fi2d = fi1d + 128;

    const int tid = threadIdx.x;
    const int pairIdx = blockIdx.x;

    const float4* r0 = (const float4*)(x + (size_t)pairIdx * 2 * 4096);
    const float4* r1 = r0 + 1024;
    for (int i = tid; i < 1024; i += 256) {
        float4 a = r0[i], b = r1[i];
        xs2[4*i + 0] = pack_f32x2(a.x, b.x);
        xs2[4*i + 1] = pack_f32x2(a.y, b.y);
        xs2[4*i + 2] = pack_f32x2(a.z, b.z);
        xs2[4*i + 3] = pack_f32x2(a.w, b.w);
    }
    if (tid < 128) {
        fi0d[tid] = dup_f32x2(fi0[tid]);
        fi1d[tid] = dup_f32x2(fi1[tid]);
        fi2d[tid] = dup_f32x2(fi2[tid]);
    }
    __syncthreads();

    // Stage A: contract F, interleaved gather (low reg pressure).
    {
        const int de = tid;
        const int4* ip4 = (const int4*)(iperm + de*16);
        ull_t acc[8];
        #pragma unroll
        for (int f = 0; f < 8; f++) acc[f] = 0ull;
        #pragma unroll
        for (int k = 0; k < 4; k++) {
            int4 p = ip4[k];
            ull_t x0 = xs2[p.x], x1 = xs2[p.y], x2 = xs2[p.z], x3 = xs2[p.w];
            #pragma unroll
            for (int f = 0; f < 8; f++) {
                acc[f] = fma_f32x2(x0, fi2d[(4*k+0)*8 + f], acc[f]);
                acc[f] = fma_f32x2(x1, fi2d[(4*k+1)*8 + f], acc[f]);
                acc[f] = fma_f32x2(x2, fi2d[(4*k+2)*8 + f], acc[f]);
                acc[f] = fma_f32x2(x3, fi2d[(4*k+3)*8 + f], acc[f]);
            }
        }
        __syncthreads();   // xs2 reads done before t1 write? t1 separate; this
                           // barrier orders xs2 reads before t2 (alias) writes
        #pragma unroll
        for (int f = 0; f < 8; f++) t1[f*257 + de] = acc[f];
    }
    __syncthreads();

    // Stage B: contract E -> t2 (aliases xs2; xs2 no longer needed).
    #pragma unroll
    for (int k = 0; k < 4; k++) {
        int idx = tid + k*256;
        int D = idx >> 6, e = (idx >> 3) & 7, f = idx & 7;
        ull_t acc = 0ull;
        #pragma unroll
        for (int E = 0; E < 16; E++)
            acc = fma_f32x2(t1[f*257 + D*16 + E], fi1d[E*8 + e], acc);
        t2[idx] = acc;
    }
    __syncthreads();

    // Stage C: contract D -> g_Y2[pair][d*64+e*8+f]
    ull_t* yout = &g_Y2[(size_t)pairIdx * 512];
    #pragma unroll
    for (int k = 0; k < 2; k++) {
        int idx = tid + k*256;
        int d = idx >> 6, ef = idx & 63;
        ull_t acc = 0ull;
        #pragma unroll
        for (int D = 0; D < 16; D++)
            acc = fma_f32x2(t2[D*64 + ef], fi0d[D*8 + d], acc);
        yout[idx] = acc;
    }
}

// ============================================================================
// Kernel 2: core GEMM.  Z2[pair][o] = sum_h Y2[pair][h] * core[o*512+h]
// Grid (NP/64, 8). CTA: 64 pairs x 64 o. Thread: 4 pairs x 4 o (32 acc regs).
// Double-buffered 16-h chunks in static smem (33KB) -> ~3 CTAs/SM.
// ============================================================================
#define GP 64
#define GO 64
#define GK 16

__global__ void __launch_bounds__(256) k_gemm(const float* __restrict__ core)
{
    __shared__ ull_t Ys[2][GK][GP + 2];    // stride 66: 16B-aligned rows
    __shared__ ull_t Cs[2][GK][GO];

    const int tid = threadIdx.x;
    const int p0 = blockIdx.x * GP;
    const int o0 = blockIdx.y * GO;

    const int lp = tid >> 2;       // 0..63 (row owner for loads)
    const int lq = tid & 3;        // 0..3  (4-elem chunk)

    const int tx = tid & 15;       // pair group: pairs tx*4..tx*4+3
    const int ty = tid >> 4;       // o group: o ty*4..ty*4+3

    // --- prologue: load chunk 0 ---
    {
        const ull_t* yg = &g_Y2[(size_t)(p0 + lp) * 512 + lq * 4];
        ulonglong2 y0 = *(const ulonglong2*)(yg);
        ulonglong2 y1 = *(const ulonglong2*)(yg + 2);
        Ys[0][lq*4+0][lp] = y0.x; Ys[0][lq*4+1][lp] = y0.y;
        Ys[0][lq*4+2][lp] = y1.x; Ys[0][lq*4+3][lp] = y1.y;
        float4 c4 = *(const float4*)(core + (size_t)(o0 + lp) * 512 + lq * 4);
        Cs[0][lq*4+0][lp] = dup_f32x2(c4.x);
        Cs[0][lq*4+1][lp] = dup_f32x2(c4.y);
        Cs[0][lq*4+2][lp] = dup_f32x2(c4.z);
        Cs[0][lq*4+3][lp] = dup_f32x2(c4.w);
    }
    __syncthreads();

    ull_t acc[4][4];
    #pragma unroll
    for (int i = 0; i < 4; i++)
        #pragma unroll
        for (int j = 0; j < 4; j++) acc[i][j] = 0ull;

    for (int kb = 0; kb < 32; kb++) {
        int b = kb & 1;
        ulonglong2 ny0, ny1; float4 nc4;
        if (kb < 31) {
            const ull_t* yg = &g_Y2[(size_t)(p0 + lp) * 512 + (kb+1)*GK + lq*4];
            ny0 = *(const ulonglong2*)(yg);
            ny1 = *(const ulonglong2*)(yg + 2);
            nc4 = *(const float4*)(core + (size_t)(o0 + lp) * 512 + (kb+1)*GK + lq*4);
        }

        #pragma unroll
        for (int hh = 0; hh < GK; hh++) {
            const ulonglong2* yp = (const ulonglong2*)&Ys[b][hh][tx*4];
            const ulonglong2* cp = (const ulonglong2*)&Cs[b][hh][ty*4];
            ulonglong2 ya = yp[0], yb = yp[1];
            ulonglong2 ca = cp[0], cb2 = cp[1];
            ull_t y[4] = {ya.x, ya.y, yb.x, yb.y};
            ull_t c[4] = {ca.x, ca.y, cb2.x, cb2.y};
            #pragma unroll
            for (int i = 0; i < 4; i++)
                #pragma unroll
                for (int j = 0; j < 4; j++)
                    acc[i][j] = fma_f32x2(y[i], c[j], acc[i][j]);
        }

        if (kb < 31) {
            int nb = b ^ 1;
            Ys[nb][lq*4+0][lp] = ny0.x; Ys[nb][lq*4+1][lp] = ny0.y;
            Ys[nb][lq*4+2][lp] = ny1.x; Ys[nb][lq*4+3][lp] = ny1.y;
            Cs[nb][lq*4+0][lp] = dup_f32x2(nc4.x);
            Cs[nb][lq*4+1][lp] = dup_f32x2(nc4.y);
            Cs[nb][lq*4+2][lp] = dup_f32x2(nc4.z);
            Cs[nb][lq*4+3][lp] = dup_f32x2(nc4.w);
        }
        __syncthreads();
    }

    // Write Z tile: 4 pairs x 4 consecutive o -> 2 STG.128 per pair.
    #pragma unroll
    for (int i = 0; i < 4; i++) {
        ull_t* zg = &g_Z2[(size_t)(p0 + tx*4 + i) * 512 + o0 + ty*4];
        ulonglong2 v0; v0.x = acc[i][0]; v0.y = acc[i][1];
        ulonglong2 v1; v1.x = acc[i][2]; v1.y = acc[i][3];
        *(ulonglong2*)(zg)     = v0;
        *(ulonglong2*)(zg + 2) = v1;
    }
}

// ============================================================================
// Kernel 3: output expansion + inv-perm + scale/bias. One CTA = one pair.
// Static smem 31.7KB -> 7 CTAs/SM. Tables via __ldg (L2-hot).
// ============================================================================
__global__ void __launch_bounds__(256) k_output(
    const float* __restrict__ fo0, const float* __restrict__ fo1,
    const float* __restrict__ fo2,
    const float* __restrict__ bias, const float* __restrict__ alpha,
    const float* __restrict__ pds, const int* __restrict__ oinv,
    float* __restrict__ out)
{
    __shared__ ull_t Zs[512];
    __shared__ ull_t e1[1024];
    __shared__ ull_t e2[2048];
    __shared__ ull_t fo0d[128], fo1d[128], fo2d[128];

    const int tid = threadIdx.x;
    const int pair = blockIdx.x;
    const float alphaV = __ldg(alpha);

    const ull_t* zsrc = &g_Z2[(size_t)pair * 512];
    #pragma unroll
    for (int k = 0; k < 2; k++) Zs[tid + k*256] = zsrc[tid + k*256];
    if (tid < 128) {
        fo0d[tid] = dup_f32x2(fo0[tid]);
        fo1d[tid] = dup_f32x2(fo1[tid]);
        fo2d[tid] = dup_f32x2(fo2[tid]);
    }
    __syncthreads();

    // Stage 1: contract c.  e1[a*128+b*16+C] = sum_c Zs[a*64+b*8+c]*fo2[C,c]
    #pragma unroll
    for (int k = 0; k < 4; k++) {
        int idx = tid + k*256;
        int a_ = idx >> 7, b_ = (idx >> 4) & 7, C_ = idx & 15;
        ull_t a1 = 0ull;
        #pragma unroll
        for (int c_ = 0; c_ < 8; c_++)
            a1 = fma_f32x2(Zs[a_*64 + b_*8 + c_], fo2d[C_*8 + c_], a1);
        e1[idx] = a1;
    }
    __syncthreads();

    // Stage 2: contract b.  e2[a*256+B*16+C] = sum_b e1[a*128+b*16+C]*fo1[B,b]
    #pragma unroll
    for (int k = 0; k < 8; k++) {
        int idx = tid + k*256;
        int a_ = idx >> 8, B_ = (idx >> 4) & 15, C_ = idx & 15;
        ull_t a2 = 0ull;
        #pragma unroll
        for (int b_ = 0; b_ < 8; b_++)
            a2 = fma_f32x2(e1[a_*128 + b_*16 + C_], fo1d[B_*8 + b_], a2);
        e2[idx] = a2;
    }
    __syncthreads();

    // Stage 3: contract a + inverse-perm gather + scale/bias + store.
    float* o0p = out + (size_t)pair * 2 * 4096;
    float* o1p = o0p + 4096;
    #pragma unroll
    for (int k = 0; k < 16; k++) {
        int j = tid + k*256;
        int o = __ldg(oinv + j);
        int A_ = o >> 8, bc = o & 255;
        ull_t a3 = 0ull;
        #pragma unroll
        for (int a_ = 0; a_ < 8; a_++)
            a3 = fma_f32x2(e2[a_*256 + bc], fo0d[A_*8 + a_], a3);
        float2 v = unpack_f32x2(a3);
        float s = __ldg(pds + j) * alphaV, bb = __ldg(bias + j);
        o0p[j] = v.x * s + bb;
        o1p[j] = v.y * s + bb;
    }
}

// ============================================================================
// Launch
// ============================================================================
extern "C" void kernel_launch(void* const* d_in, const int* in_sizes, int n_in,
                              void* d_out, int out_size)
{
    const float* x     = (const float*)d_in[0];
    const float* core  = (const float*)d_in[1];
    const float* fo0   = (const float*)d_in[2];
    const float* fo1   = (const float*)d_in[3];
    const float* fo2   = (const float*)d_in[4];
    const float* fi0   = (const float*)d_in[5];
    const float* fi1   = (const float*)d_in[6];
    const float* fi2   = (const float*)d_in[7];
    const float* bias  = (const float*)d_in[8];
    const float* alpha = (const float*)d_in[9];
    const float* pds   = (const float*)d_in[10];
    const int*   iperm = (const int*)d_in[11];
    const int*   oinv  = (const int*)d_in[12];
    float* out = (float*)d_out;

    int NT = in_sizes[0] / 4096;      // tokens (8192)
    int nPairs = NT / 2;              // 4096

    cudaFuncSetAttribute(k_input, cudaFuncAttributeMaxDynamicSharedMemorySize,
                         K1_SMEM_BYTES);

    k_input<<<nPairs, 256, K1_SMEM_BYTES>>>(x, iperm, fi0, fi1, fi2);
    dim3 ggrid(nPairs / GP, 512 / GO);
    k_gemm<<<ggrid, 256>>>(core);
    k_output<<<nPairs, 256>>>(fo0, fo1, fo2, bias, alpha, pds, oinv, out);
}

// round 4
// speedup vs baseline: 1.5349x; 1.5084x over previous
#include <cuda_runtime.h>
#include <cstdint>

// ----------------------------------------------------------------------------
// TuckerLinear on GB300 (sm_103a) — 3-kernel pipeline, f32x2 packed token pairs
// ----------------------------------------------------------------------------

typedef unsigned long long ull_t;

__device__ __forceinline__ ull_t dup_f32x2(float v) {
    ull_t r; unsigned int b = __float_as_uint(v);
    asm("mov.b64 %0, {%1, %1};" : "=l"(r) : "r"(b));
    return r;
}
__device__ __forceinline__ ull_t pack_f32x2(float a, float b) {
    ull_t r;
    asm("mov.b64 %0, {%1, %2};" : "=l"(r)
        : "r"(__float_as_uint(a)), "r"(__float_as_uint(b)));
    return r;
}
__device__ __forceinline__ float2 unpack_f32x2(ull_t v) {
    unsigned int lo, hi;
    asm("mov.b64 {%0, %1}, %2;" : "=r"(lo), "=r"(hi) : "l"(v));
    return make_float2(__uint_as_float(lo), __uint_as_float(hi));
}
__device__ __forceinline__ ull_t fma_f32x2(ull_t a, ull_t b, ull_t c) {
    ull_t d;
    asm("fma.rn.f32x2 %0, %1, %2, %3;" : "=l"(d) : "l"(a), "l"(b), "l"(c));
    return d;
}

// Scratch (packed token pairs): 4096 pairs x 512 cols each.
__device__ ull_t g_Y2[4096 * 512];
__device__ ull_t g_Z2[4096 * 512];

// ============================================================================
// Kernel 1: gather + input-side contractions. One CTA = TWO token pairs
// (factor loads amortized over 2 pairs). 256 threads.
// smem: xs2[2][4096] (t2 aliases head of each), t1[2][8*257], fi tables.
// ============================================================================
#define K1_SMEM_ULL (2*4096 + 2*8*257 + 3*128)
#define K1_SMEM_BYTES (K1_SMEM_ULL * 8)

__global__ void __launch_bounds__(256) k_input(
    const float* __restrict__ x, const int* __restrict__ iperm,
    const float* __restrict__ fi0, const float* __restrict__ fi1,
    const float* __restrict__ fi2)
{
    extern __shared__ __align__(16) char smem_raw[];
    ull_t* xs2a = (ull_t*)smem_raw;          // [4096] pair A (t2a aliases head)
    ull_t* xs2b = xs2a + 4096;               // [4096] pair B
    ull_t* t2a  = xs2a;
    ull_t* t2b  = xs2b;
    ull_t* t1a  = xs2b + 4096;               // [8*257]
    ull_t* t1b  = t1a + 8*257;
    ull_t* fi0d = t1b + 8*257;
    ull_t* fi1d = fi0d + 128;
    ull_t* fi2d = fi1d + 128;

    const int tid = threadIdx.x;
    const int pair0 = blockIdx.x * 2;

    // Load 4 token rows coalesced, pack into f32x2 per pair.
    const float4* r0 = (const float4*)(x + (size_t)pair0 * 2 * 4096);
    const float4* r1 = r0 + 1024;
    const float4* r2 = r1 + 1024;
    const float4* r3 = r2 + 1024;
    for (int i = tid; i < 1024; i += 256) {
        float4 a = r0[i], b = r1[i], c = r2[i], d = r3[i];
        xs2a[4*i+0] = pack_f32x2(a.x, b.x); xs2a[4*i+1] = pack_f32x2(a.y, b.y);
        xs2a[4*i+2] = pack_f32x2(a.z, b.z); xs2a[4*i+3] = pack_f32x2(a.w, b.w);
        xs2b[4*i+0] = pack_f32x2(c.x, d.x); xs2b[4*i+1] = pack_f32x2(c.y, d.y);
        xs2b[4*i+2] = pack_f32x2(c.z, d.z); xs2b[4*i+3] = pack_f32x2(c.w, d.w);
    }
    if (tid < 128) {
        fi0d[tid] = dup_f32x2(fi0[tid]);
        fi1d[tid] = dup_f32x2(fi1[tid]);
        fi2d[tid] = dup_f32x2(fi2[tid]);
    }
    __syncthreads();

    // Stage A: contract F. thread = de; both pairs share gathers' indices
    // and factor broadcasts.
    {
        const int de = tid;
        const int4* ip4 = (const int4*)(iperm + de*16);
        ull_t accA[8], accB[8];
        #pragma unroll
        for (int f = 0; f < 8; f++) { accA[f] = 0ull; accB[f] = 0ull; }
        #pragma unroll
        for (int k = 0; k < 4; k++) {
            int4 p = ip4[k];
            ull_t ax = xs2a[p.x], ay = xs2a[p.y], az = xs2a[p.z], aw = xs2a[p.w];
            ull_t bx = xs2b[p.x], by = xs2b[p.y], bz = xs2b[p.z], bw = xs2b[p.w];
            #pragma unroll
            for (int f = 0; f < 8; f++) {
                ull_t w0 = fi2d[(4*k+0)*8 + f];
                accA[f] = fma_f32x2(ax, w0, accA[f]);
                accB[f] = fma_f32x2(bx, w0, accB[f]);
                ull_t w1 = fi2d[(4*k+1)*8 + f];
                accA[f] = fma_f32x2(ay, w1, accA[f]);
                accB[f] = fma_f32x2(by, w1, accB[f]);
                ull_t w2 = fi2d[(4*k+2)*8 + f];
                accA[f] = fma_f32x2(az, w2, accA[f]);
                accB[f] = fma_f32x2(bz, w2, accB[f]);
                ull_t w3 = fi2d[(4*k+3)*8 + f];
                accA[f] = fma_f32x2(aw, w3, accA[f]);
                accB[f] = fma_f32x2(bw, w3, accB[f]);
            }
        }
        #pragma unroll
        for (int f = 0; f < 8; f++) {
            t1a[f*257 + de] = accA[f];
            t1b[f*257 + de] = accB[f];
        }
    }
    __syncthreads();

    // Stage B: contract E -> t2 (aliases xs2; xs2 dead after stage A).
    #pragma unroll
    for (int k = 0; k < 4; k++) {
        int idx = tid + k*256;
        int D = idx >> 6, e = (idx >> 3) & 7, f = idx & 7;
        ull_t aA = 0ull, aB = 0ull;
        #pragma unroll
        for (int E = 0; E < 16; E++) {
            ull_t w = fi1d[E*8 + e];
            aA = fma_f32x2(t1a[f*257 + D*16 + E], w, aA);
            aB = fma_f32x2(t1b[f*257 + D*16 + E], w, aB);
        }
        t2a[idx] = aA;
        t2b[idx] = aB;
    }
    __syncthreads();

    // Stage C: contract D -> g_Y2
    ull_t* youtA = &g_Y2[(size_t)pair0 * 512];
    ull_t* youtB = youtA + 512;
    #pragma unroll
    for (int k = 0; k < 2; k++) {
        int idx = tid + k*256;
        int d = idx >> 6, ef = idx & 63;
        ull_t aA = 0ull, aB = 0ull;
        #pragma unroll
        for (int D = 0; D < 16; D++) {
            ull_t w = fi0d[D*8 + d];
            aA = fma_f32x2(t2a[D*64 + ef], w, aA);
            aB = fma_f32x2(t2b[D*64 + ef], w, aB);
        }
        youtA[idx] = aA;
        youtB[idx] = aB;
    }
}

// ============================================================================
// Kernel 2: core GEMM. Z2[pair][o] = sum_h Y2[pair][h] * core[o*512+h]
// CTA: 64 pairs x 64 o, 256 thr, 2 CTAs/SM. Thread: 4p x 4o.
// Warp layout: pgrp=(wid&1)*8+(lane&7), ogrp=(wid>>1)*4+(lane>>3)
//   -> y LDS 1-phase (8 distinct 16B), c LDS broadcast (4 distinct).
// ============================================================================
#define GP 64
#define GO 64
#define GK 16

__global__ void __launch_bounds__(256, 2) k_gemm(const float* __restrict__ core)
{
    __shared__ __align__(16) ull_t Ys[2][GK][66];
    __shared__ __align__(16) ull_t Cs[2][GK][66];

    const int tid = threadIdx.x;
    const int p0 = blockIdx.x * GP;
    const int o0 = blockIdx.y * GO;

    const int lp = tid >> 2;       // 0..63 row owner for loads
    const int lq = tid & 3;        // 0..3  4-elem chunk
    const int wid = tid >> 5, lane = tid & 31;
    const int pgrp = (wid & 1) * 8 + (lane & 7);    // 0..15
    const int ogrp = (wid >> 1) * 4 + (lane >> 3);  // 0..15

    // prologue: chunk 0
    {
        const ull_t* yg = &g_Y2[(size_t)(p0 + lp) * 512 + lq * 4];
        ulonglong2 y0 = *(const ulonglong2*)(yg);
        ulonglong2 y1 = *(const ulonglong2*)(yg + 2);
        Ys[0][lq*4+0][lp] = y0.x; Ys[0][lq*4+1][lp] = y0.y;
        Ys[0][lq*4+2][lp] = y1.x; Ys[0][lq*4+3][lp] = y1.y;
        float4 c4 = *(const float4*)(core + (size_t)(o0 + lp) * 512 + lq * 4);
        Cs[0][lq*4+0][lp] = dup_f32x2(c4.x);
        Cs[0][lq*4+1][lp] = dup_f32x2(c4.y);
        Cs[0][lq*4+2][lp] = dup_f32x2(c4.z);
        Cs[0][lq*4+3][lp] = dup_f32x2(c4.w);
    }
    __syncthreads();

    ull_t acc[4][4];
    #pragma unroll
    for (int i = 0; i < 4; i++)
        #pragma unroll
        for (int j = 0; j < 4; j++) acc[i][j] = 0ull;

    for (int kb = 0; kb < 32; kb++) {
        int b = kb & 1;
        ulonglong2 ny0, ny1; float4 nc4;
        if (kb < 31) {
            const ull_t* yg = &g_Y2[(size_t)(p0 + lp) * 512 + (kb+1)*GK + lq*4];
            ny0 = *(const ulonglong2*)(yg);
            ny1 = *(const ulonglong2*)(yg + 2);
            nc4 = *(const float4*)(core + (size_t)(o0 + lp) * 512 + (kb+1)*GK + lq*4);
        }

        #pragma unroll
        for (int hh = 0; hh < GK; hh++) {
            ulonglong2 ya = *(const ulonglong2*)&Ys[b][hh][pgrp*4];
            ulonglong2 yb = *(const ulonglong2*)&Ys[b][hh][pgrp*4 + 2];
            ulonglong2 ca = *(const ulonglong2*)&Cs[b][hh][ogrp*4];
            ulonglong2 cb = *(const ulonglong2*)&Cs[b][hh][ogrp*4 + 2];
            ull_t y[4] = {ya.x, ya.y, yb.x, yb.y};
            ull_t c[4] = {ca.x, ca.y, cb.x, cb.y};
            #pragma unroll
            for (int i = 0; i < 4; i++)
                #pragma unroll
                for (int j = 0; j < 4; j++)
                    acc[i][j] = fma_f32x2(y[i], c[j], acc[i][j]);
        }

        if (kb < 31) {
            int nb = b ^ 1;
            Ys[nb][lq*4+0][lp] = ny0.x; Ys[nb][lq*4+1][lp] = ny0.y;
            Ys[nb][lq*4+2][lp] = ny1.x; Ys[nb][lq*4+3][lp] = ny1.y;
            Cs[nb][lq*4+0][lp] = dup_f32x2(nc4.x);
            Cs[nb][lq*4+1][lp] = dup_f32x2(nc4.y);
            Cs[nb][lq*4+2][lp] = dup_f32x2(nc4.z);
            Cs[nb][lq*4+3][lp] = dup_f32x2(nc4.w);
        }
        __syncthreads();
    }

    #pragma unroll
    for (int i = 0; i < 4; i++) {
        ull_t* zg = &g_Z2[(size_t)(p0 + pgrp*4 + i) * 512 + o0 + ogrp*4];
        ulonglong2 v0; v0.x = acc[i][0]; v0.y = acc[i][1];
        ulonglong2 v1; v1.x = acc[i][2]; v1.y = acc[i][3];
        *(ulonglong2*)(zg)     = v0;
        *(ulonglong2*)(zg + 2) = v1;
    }
}

// ============================================================================
// Kernel 3: output expansion. One CTA = one pair. Natural-order compute into
// arr[], then separate permuted read (1 random LDS per output).
// ============================================================================
#define K3_SMEM_ULL (512 + 1024 + 2048 + 4096 + 3*128)
#define K3_SMEM_BYTES (K3_SMEM_ULL * 8)

__global__ void __launch_bounds__(256) k_output(
    const float* __restrict__ fo0, const float* __restrict__ fo1,
    const float* __restrict__ fo2,
    const float* __restrict__ bias, const float* __restrict__ alpha,
    const float* __restrict__ pds, const int* __restrict__ oinv,
    float* __restrict__ out)
{
    extern __shared__ __align__(16) char smem3[];
    ull_t* Zs   = (ull_t*)smem3;          // [512]
    ull_t* e1   = Zs + 512;               // [1024]  [a*128+b*16+C]
    ull_t* e2   = e1 + 1024;              // [2048]  [a*256+bc]
    ull_t* arr  = e2 + 2048;              // [4096]  natural-order result
    ull_t* fo0d = arr + 4096;             // [128]
    ull_t* fo1d = fo0d + 128;
    ull_t* fo2t = fo1d + 128;             // [c*16+C] transposed

    const int tid = threadIdx.x;
    const int pair = blockIdx.x;
    const float alphaV = __ldg(alpha);

    const ull_t* zsrc = &g_Z2[(size_t)pair * 512];
    #pragma unroll
    for (int k = 0; k < 2; k++) Zs[tid + k*256] = zsrc[tid + k*256];
    if (tid < 128) {
        fo0d[tid] = dup_f32x2(fo0[tid]);
        fo1d[tid] = dup_f32x2(fo1[tid]);
        int C_ = tid >> 3, c_ = tid & 7;          // fo2[C*8+c] -> fo2t[c*16+C]
        fo2t[c_*16 + C_] = dup_f32x2(fo2[tid]);
    }
    __syncthreads();

    // Stage 1: contract c. e1[a*128+b*16+C] = sum_c Zs[a*64+b*8+c]*fo2[C,c]
    #pragma unroll
    for (int k = 0; k < 4; k++) {
        int idx = tid + k*256;
        int a_ = idx >> 7, b_ = (idx >> 4) & 7, C_ = idx & 15;
        ull_t a1 = 0ull;
        #pragma unroll
        for (int c_ = 0; c_ < 8; c_++)
            a1 = fma_f32x2(Zs[a_*64 + b_*8 + c_], fo2t[c_*16 + C_], a1);
        e1[idx] = a1;
    }
    __syncthreads();

    // Stage 2: contract b. e2[a*256 + B*16 + C] = sum_b e1[a*128+b*16+C]*fo1[B,b]
    #pragma unroll
    for (int k = 0; k < 8; k++) {
        int idx = tid + k*256;
        int a_ = idx >> 8, bc = idx & 255;
        int B_ = bc >> 4, C_ = bc & 15;
        ull_t a2 = 0ull;
        #pragma unroll
        for (int b_ = 0; b_ < 8; b_++)
            a2 = fma_f32x2(e1[a_*128 + b_*16 + C_], fo1d[B_*8 + b_], a2);
        e2[idx] = a2;
    }
    __syncthreads();

    // Stage 3a: contract a in NATURAL order (sequential e2, broadcast fo0).
    #pragma unroll
    for (int k = 0; k < 16; k++) {
        int n = tid + k*256;
        int A_ = n >> 8, bc = n & 255;
        ull_t a3 = 0ull;
        #pragma unroll
        for (int a_ = 0; a_ < 8; a_++)
            a3 = fma_f32x2(e2[a_*256 + bc], fo0d[A_*8 + a_], a3);
        arr[n] = a3;
    }
    __syncthreads();

    // Stage 3b: permuted read + scale/bias + coalesced store.
    float* o0p = out + (size_t)pair * 2 * 4096;
    float* o1p = o0p + 4096;
    #pragma unroll
    for (int k = 0; k < 16; k++) {
        int j = tid + k*256;
        int o = __ldg(oinv + j);
        float2 v = unpack_f32x2(arr[o]);
        float s = __ldg(pds + j) * alphaV, bb = __ldg(bias + j);
        o0p[j] = v.x * s + bb;
        o1p[j] = v.y * s + bb;
    }
}

// ============================================================================
// Launch
// ============================================================================
extern "C" void kernel_launch(void* const* d_in, const int* in_sizes, int n_in,
                              void* d_out, int out_size)
{
    const float* x     = (const float*)d_in[0];
    const float* core  = (const float*)d_in[1];
    const float* fo0   = (const float*)d_in[2];
    const float* fo1   = (const float*)d_in[3];
    const float* fo2   = (const float*)d_in[4];
    const float* fi0   = (const float*)d_in[5];
    const float* fi1   = (const float*)d_in[6];
    const float* fi2   = (const float*)d_in[7];
    const float* bias  = (const float*)d_in[8];
    const float* alpha = (const float*)d_in[9];
    const float* pds   = (const float*)d_in[10];
    const int*   iperm = (const int*)d_in[11];
    const int*   oinv  = (const int*)d_in[12];
    float* out = (float*)d_out;

    int NT = in_sizes[0] / 4096;      // tokens (8192)
    int nPairs = NT / 2;              // 4096

    cudaFuncSetAttribute(k_input, cudaFuncAttributeMaxDynamicSharedMemorySize,
                         K1_SMEM_BYTES);
    cudaFuncSetAttribute(k_output, cudaFuncAttributeMaxDynamicSharedMemorySize,
                         K3_SMEM_BYTES);

    k_input<<<nPairs/2, 256, K1_SMEM_BYTES>>>(x, iperm, fi0, fi1, fi2);
    dim3 ggrid(nPairs / GP, 512 / GO);
    k_gemm<<<ggrid, 256>>>(core);
    k_output<<<nPairs, 256, K3_SMEM_BYTES>>>(fo0, fo1, fo2, bias, alpha, pds,
                                             oinv, out);
}

// round 5
// speedup vs baseline: 1.8473x; 1.2035x over previous
#include <cuda_runtime.h>
#include <cstdint>

// ----------------------------------------------------------------------------
// TuckerLinear on GB300 (sm_103a) — 3-kernel pipeline, f32x2 packed token pairs
// ----------------------------------------------------------------------------

typedef unsigned long long ull_t;

__device__ __forceinline__ ull_t dup_f32x2(float v) {
    ull_t r; unsigned int b = __float_as_uint(v);
    asm("mov.b64 %0, {%1, %1};" : "=l"(r) : "r"(b));
    return r;
}
__device__ __forceinline__ ull_t pack_f32x2(float a, float b) {
    ull_t r;
    asm("mov.b64 %0, {%1, %2};" : "=l"(r)
        : "r"(__float_as_uint(a)), "r"(__float_as_uint(b)));
    return r;
}
__device__ __forceinline__ float2 unpack_f32x2(ull_t v) {
    unsigned int lo, hi;
    asm("mov.b64 {%0, %1}, %2;" : "=r"(lo), "=r"(hi) : "l"(v));
    return make_float2(__uint_as_float(lo), __uint_as_float(hi));
}
__device__ __forceinline__ ull_t fma_f32x2(ull_t a, ull_t b, ull_t c) {
    ull_t d;
    asm("fma.rn.f32x2 %0, %1, %2, %3;" : "=l"(d) : "l"(a), "l"(b), "l"(c));
    return d;
}

// Scratch (packed token pairs): 4096 pairs x 512 cols each.
__device__ ull_t g_Y2[4096 * 512];
__device__ ull_t g_Z2[4096 * 512];

// ============================================================================
// Kernel 1: gather + input-side contractions. One CTA = TWO token pairs.
// ============================================================================
#define K1_SMEM_ULL (2*4096 + 2*8*257 + 3*128)
#define K1_SMEM_BYTES (K1_SMEM_ULL * 8)

__global__ void __launch_bounds__(256) k_input(
    const float* __restrict__ x, const int* __restrict__ iperm,
    const float* __restrict__ fi0, const float* __restrict__ fi1,
    const float* __restrict__ fi2)
{
    extern __shared__ __align__(16) char smem_raw[];
    ull_t* xs2a = (ull_t*)smem_raw;          // [4096] pair A (t2a aliases head)
    ull_t* xs2b = xs2a + 4096;               // [4096] pair B
    ull_t* t2a  = xs2a;
    ull_t* t2b  = xs2b;
    ull_t* t1a  = xs2b + 4096;               // [8*257]
    ull_t* t1b  = t1a + 8*257;
    ull_t* fi0d = t1b + 8*257;
    ull_t* fi1d = fi0d + 128;
    ull_t* fi2d = fi1d + 128;

    const int tid = threadIdx.x;
    const int pair0 = blockIdx.x * 2;

    const float4* r0 = (const float4*)(x + (size_t)pair0 * 2 * 4096);
    const float4* r1 = r0 + 1024;
    const float4* r2 = r1 + 1024;
    const float4* r3 = r2 + 1024;
    for (int i = tid; i < 1024; i += 256) {
        float4 a = r0[i], b = r1[i], c = r2[i], d = r3[i];
        xs2a[4*i+0] = pack_f32x2(a.x, b.x); xs2a[4*i+1] = pack_f32x2(a.y, b.y);
        xs2a[4*i+2] = pack_f32x2(a.z, b.z); xs2a[4*i+3] = pack_f32x2(a.w, b.w);
        xs2b[4*i+0] = pack_f32x2(c.x, d.x); xs2b[4*i+1] = pack_f32x2(c.y, d.y);
        xs2b[4*i+2] = pack_f32x2(c.z, d.z); xs2b[4*i+3] = pack_f32x2(c.w, d.w);
    }
    if (tid < 128) {
        fi0d[tid] = dup_f32x2(fi0[tid]);
        fi1d[tid] = dup_f32x2(fi1[tid]);
        fi2d[tid] = dup_f32x2(fi2[tid]);
    }
    __syncthreads();

    // Stage A: contract F.
    {
        const int de = tid;
        const int4* ip4 = (const int4*)(iperm + de*16);
        ull_t accA[8], accB[8];
        #pragma unroll
        for (int f = 0; f < 8; f++) { accA[f] = 0ull; accB[f] = 0ull; }
        #pragma unroll
        for (int k = 0; k < 4; k++) {
            int4 p = ip4[k];
            ull_t ax = xs2a[p.x], ay = xs2a[p.y], az = xs2a[p.z], aw = xs2a[p.w];
            ull_t bx = xs2b[p.x], by = xs2b[p.y], bz = xs2b[p.z], bw = xs2b[p.w];
            #pragma unroll
            for (int f = 0; f < 8; f++) {
                ull_t w0 = fi2d[(4*k+0)*8 + f];
                accA[f] = fma_f32x2(ax, w0, accA[f]);
                accB[f] = fma_f32x2(bx, w0, accB[f]);
                ull_t w1 = fi2d[(4*k+1)*8 + f];
                accA[f] = fma_f32x2(ay, w1, accA[f]);
                accB[f] = fma_f32x2(by, w1, accB[f]);
                ull_t w2 = fi2d[(4*k+2)*8 + f];
                accA[f] = fma_f32x2(az, w2, accA[f]);
                accB[f] = fma_f32x2(bz, w2, accB[f]);
                ull_t w3 = fi2d[(4*k+3)*8 + f];
                accA[f] = fma_f32x2(aw, w3, accA[f]);
                accB[f] = fma_f32x2(bw, w3, accB[f]);
            }
        }
        #pragma unroll
        for (int f = 0; f < 8; f++) {
            t1a[f*257 + de] = accA[f];
            t1b[f*257 + de] = accB[f];
        }
    }
    __syncthreads();

    // Stage B: contract E -> t2 (aliases xs2).
    #pragma unroll
    for (int k = 0; k < 4; k++) {
        int idx = tid + k*256;
        int D = idx >> 6, e = (idx >> 3) & 7, f = idx & 7;
        ull_t aA = 0ull, aB = 0ull;
        #pragma unroll
        for (int E = 0; E < 16; E++) {
            ull_t w = fi1d[E*8 + e];
            aA = fma_f32x2(t1a[f*257 + D*16 + E], w, aA);
            aB = fma_f32x2(t1b[f*257 + D*16 + E], w, aB);
        }
        t2a[idx] = aA;
        t2b[idx] = aB;
    }
    __syncthreads();

    // Stage C: contract D -> g_Y2
    ull_t* youtA = &g_Y2[(size_t)pair0 * 512];
    ull_t* youtB = youtA + 512;
    #pragma unroll
    for (int k = 0; k < 2; k++) {
        int idx = tid + k*256;
        int d = idx >> 6, ef = idx & 63;
        ull_t aA = 0ull, aB = 0ull;
        #pragma unroll
        for (int D = 0; D < 16; D++) {
            ull_t w = fi0d[D*8 + d];
            aA = fma_f32x2(t2a[D*64 + ef], w, aA);
            aB = fma_f32x2(t2b[D*64 + ef], w, aB);
        }
        youtA[idx] = aA;
        youtB[idx] = aB;
    }
}

// ============================================================================
// Kernel 2: core GEMM. CTA: 64 pairs x 128 o, 256 thr, 2 CTAs/SM.
// Thread tile: 4 pairs x 8 o (64 acc regs). Grid (64, 4).
// ============================================================================
#define GP 64
#define GO 128
#define GK 16

__global__ void __launch_bounds__(256, 2) k_gemm(const float* __restrict__ core)
{
    __shared__ __align__(16) ull_t Ys[2][GK][66];
    __shared__ __align__(16) ull_t Cs[2][GK][130];

    const int tid = threadIdx.x;
    const int p0 = blockIdx.x * GP;
    const int o0 = blockIdx.y * GO;

    const int yrow = tid >> 2, yq = tid & 3;       // Y loads: 64 rows x 4 chunks
    const int crow = tid >> 1, ch = tid & 1;       // C loads: 128 rows x 2 halves
    const int wid = tid >> 5, lane = tid & 31;
    const int pgrp = (lane & 7) + (wid & 1) * 8;   // 0..15 -> pairs pgrp*4..+3
    const int ogrp = (lane >> 3) + (wid >> 1) * 4; // 0..15 -> o ogrp*8..+7

    // prologue: chunk 0
    {
        const ull_t* yg = &g_Y2[(size_t)(p0 + yrow) * 512 + yq * 4];
        ulonglong2 y0 = *(const ulonglong2*)(yg);
        ulonglong2 y1 = *(const ulonglong2*)(yg + 2);
        Ys[0][yq*4+0][yrow] = y0.x; Ys[0][yq*4+1][yrow] = y0.y;
        Ys[0][yq*4+2][yrow] = y1.x; Ys[0][yq*4+3][yrow] = y1.y;
        const float4* cg = (const float4*)(core + (size_t)(o0 + crow) * 512 + ch * 8);
        float4 c0 = cg[0], c1 = cg[1];
        Cs[0][ch*8+0][crow] = dup_f32x2(c0.x); Cs[0][ch*8+1][crow] = dup_f32x2(c0.y);
        Cs[0][ch*8+2][crow] = dup_f32x2(c0.z); Cs[0][ch*8+3][crow] = dup_f32x2(c0.w);
        Cs[0][ch*8+4][crow] = dup_f32x2(c1.x); Cs[0][ch*8+5][crow] = dup_f32x2(c1.y);
        Cs[0][ch*8+6][crow] = dup_f32x2(c1.z); Cs[0][ch*8+7][crow] = dup_f32x2(c1.w);
    }
    __syncthreads();

    ull_t acc[4][8];
    #pragma unroll
    for (int i = 0; i < 4; i++)
        #pragma unroll
        for (int j = 0; j < 8; j++) acc[i][j] = 0ull;

    for (int kb = 0; kb < 32; kb++) {
        int b = kb & 1;
        ulonglong2 ny0, ny1; float4 nc0, nc1;
        if (kb < 31) {
            const ull_t* yg = &g_Y2[(size_t)(p0 + yrow) * 512 + (kb+1)*GK + yq*4];
            ny0 = *(const ulonglong2*)(yg);
            ny1 = *(const ulonglong2*)(yg + 2);
            const float4* cg = (const float4*)(core + (size_t)(o0 + crow) * 512
                                               + (kb+1)*GK + ch * 8);
            nc0 = cg[0]; nc1 = cg[1];
        }

        #pragma unroll
        for (int hh = 0; hh < GK; hh++) {
            ulonglong2 ya = *(const ulonglong2*)&Ys[b][hh][pgrp*4];
            ulonglong2 yb = *(const ulonglong2*)&Ys[b][hh][pgrp*4 + 2];
            ulonglong2 c0 = *(const ulonglong2*)&Cs[b][hh][ogrp*8];
            ulonglong2 c1 = *(const ulonglong2*)&Cs[b][hh][ogrp*8 + 2];
            ulonglong2 c2 = *(const ulonglong2*)&Cs[b][hh][ogrp*8 + 4];
            ulonglong2 c3 = *(const ulonglong2*)&Cs[b][hh][ogrp*8 + 6];
            ull_t y[4] = {ya.x, ya.y, yb.x, yb.y};
            ull_t c[8] = {c0.x, c0.y, c1.x, c1.y, c2.x, c2.y, c3.x, c3.y};
            #pragma unroll
            for (int i = 0; i < 4; i++)
                #pragma unroll
                for (int j = 0; j < 8; j++)
                    acc[i][j] = fma_f32x2(y[i], c[j], acc[i][j]);
        }

        if (kb < 31) {
            int nb = b ^ 1;
            Ys[nb][yq*4+0][yrow] = ny0.x; Ys[nb][yq*4+1][yrow] = ny0.y;
            Ys[nb][yq*4+2][yrow] = ny1.x; Ys[nb][yq*4+3][yrow] = ny1.y;
            Cs[nb][ch*8+0][crow] = dup_f32x2(nc0.x);
            Cs[nb][ch*8+1][crow] = dup_f32x2(nc0.y);
            Cs[nb][ch*8+2][crow] = dup_f32x2(nc0.z);
            Cs[nb][ch*8+3][crow] = dup_f32x2(nc0.w);
            Cs[nb][ch*8+4][crow] = dup_f32x2(nc1.x);
            Cs[nb][ch*8+5][crow] = dup_f32x2(nc1.y);
            Cs[nb][ch*8+6][crow] = dup_f32x2(nc1.z);
            Cs[nb][ch*8+7][crow] = dup_f32x2(nc1.w);
        }
        __syncthreads();
    }

    #pragma unroll
    for (int i = 0; i < 4; i++) {
        ull_t* zg = &g_Z2[(size_t)(p0 + pgrp*4 + i) * 512 + o0 + ogrp*8];
        ulonglong2 v;
        v.x = acc[i][0]; v.y = acc[i][1]; *(ulonglong2*)(zg)     = v;
        v.x = acc[i][2]; v.y = acc[i][3]; *(ulonglong2*)(zg + 2) = v;
        v.x = acc[i][4]; v.y = acc[i][5]; *(ulonglong2*)(zg + 4) = v;
        v.x = acc[i][6]; v.y = acc[i][7]; *(ulonglong2*)(zg + 6) = v;
    }
}

// ============================================================================
// Kernel 3: output expansion. One CTA = one pair. Register-blocked stages
// with transposed fo tables (vector weight loads feed 2 FMAs each).
// ============================================================================
#define K3_SMEM_ULL (512 + 64*17 + 2048 + 16*257 + 3*128)
#define K3_SMEM_BYTES (K3_SMEM_ULL * 8)

__global__ void __launch_bounds__(256) k_output(
    const float* __restrict__ fo0, const float* __restrict__ fo1,
    const float* __restrict__ fo2,
    const float* __restrict__ bias, const float* __restrict__ alpha,
    const float* __restrict__ pds, const int* __restrict__ oinv,
    float* __restrict__ out)
{
    extern __shared__ __align__(16) char smem3[];
    ull_t* Zs   = (ull_t*)smem3;          // [512]  [a*64+b*8+c]
    ull_t* e1   = Zs + 512;               // [64*17]  [(a*8+b)*17 + C]
    ull_t* e2   = e1 + 64*17;             // [2048]   [a*256 + B*16 + C]
    ull_t* arr  = e2 + 2048;              // [16*257] [A*257 + bc]
    ull_t* fo0t = arr + 16*257;           // [a*16+A]
    ull_t* fo1t = fo0t + 128;             // [b*16+B]
    ull_t* fo2t = fo1t + 128;             // [c*16+C]

    const int tid = threadIdx.x;
    const int pair = blockIdx.x;
    const float alphaV = __ldg(alpha);

    const ull_t* zsrc = &g_Z2[(size_t)pair * 512];
    #pragma unroll
    for (int k = 0; k < 2; k++) Zs[tid + k*256] = zsrc[tid + k*256];
    if (tid < 128) {
        int M_ = tid >> 3, r_ = tid & 7;      // f[M,r] -> ft[r*16+M]
        fo0t[r_*16 + M_] = dup_f32x2(fo0[tid]);
        fo1t[r_*16 + M_] = dup_f32x2(fo1[tid]);
        fo2t[r_*16 + M_] = dup_f32x2(fo2[tid]);
    }
    __syncthreads();

    // Stage 1: contract c. Thread tile 2(ab) x 2(C).
    {
        int ab0 = (tid >> 3) * 2;
        int C0  = (tid & 7) * 2;
        ull_t a00 = 0, a01 = 0, a10 = 0, a11 = 0;
        #pragma unroll
        for (int c_ = 0; c_ < 8; c_++) {
            ull_t z0 = Zs[ab0*8 + c_];
            ull_t z1 = Zs[(ab0+1)*8 + c_];
            ulonglong2 w = *(const ulonglong2*)&fo2t[c_*16 + C0];
            a00 = fma_f32x2(z0, w.x, a00); a01 = fma_f32x2(z0, w.y, a01);
            a10 = fma_f32x2(z1, w.x, a10); a11 = fma_f32x2(z1, w.y, a11);
        }
        e1[ab0*17 + C0]       = a00;
        e1[ab0*17 + C0 + 1]   = a01;
        e1[(ab0+1)*17 + C0]   = a10;
        e1[(ab0+1)*17 + C0+1] = a11;
    }
    __syncthreads();

    // Stage 2: contract b. Thread tile 8(B), fixed (a, C).
    {
        int a_ = tid >> 5;
        int C_ = (tid >> 1) & 15;
        int B0 = (tid & 1) * 8;
        ull_t acc[8];
        #pragma unroll
        for (int j = 0; j < 8; j++) acc[j] = 0ull;
        #pragma unroll
        for (int b_ = 0; b_ < 8; b_++) {
            ull_t ev = e1[(a_*8 + b_)*17 + C_];
            #pragma unroll
            for (int j = 0; j < 4; j++) {
                ulonglong2 w = *(const ulonglong2*)&fo1t[b_*16 + B0 + 2*j];
                acc[2*j]   = fma_f32x2(ev, w.x, acc[2*j]);
                acc[2*j+1] = fma_f32x2(ev, w.y, acc[2*j+1]);
            }
        }
        #pragma unroll
        for (int j = 0; j < 8; j++)
            e2[a_*256 + (B0+j)*16 + C_] = acc[j];
    }
    __syncthreads();

    // Stage 3a: contract a (natural order). Thread tile 2(bc) x 8(A).
    {
        int bc0 = (tid >> 1) * 2;
        int A0  = (tid & 1) * 8;
        ull_t acc[2][8];
        #pragma unroll
        for (int i = 0; i < 2; i++)
            #pragma unroll
            for (int j = 0; j < 8; j++) acc[i][j] = 0ull;
        #pragma unroll
        for (int a_ = 0; a_ < 8; a_++) {
            ull_t z0 = e2[a_*256 + bc0];
            ull_t z1 = e2[a_*256 + bc0 + 1];
            #pragma unroll
            for (int j = 0; j < 4; j++) {
                ulonglong2 w = *(const ulonglong2*)&fo0t[a_*16 + A0 + 2*j];
                acc[0][2*j]   = fma_f32x2(z0, w.x, acc[0][2*j]);
                acc[0][2*j+1] = fma_f32x2(z0, w.y, acc[0][2*j+1]);
                acc[1][2*j]   = fma_f32x2(z1, w.x, acc[1][2*j]);
                acc[1][2*j+1] = fma_f32x2(z1, w.y, acc[1][2*j+1]);
            }
        }
        #pragma unroll
        for (int j = 0; j < 8; j++) {
            arr[(A0+j)*257 + bc0]     = acc[0][j];
            arr[(A0+j)*257 + bc0 + 1] = acc[1][j];
        }
    }
    __syncthreads();

    // Stage 3b: permuted read + scale/bias + coalesced store.
    float* o0p = out + (size_t)pair * 2 * 4096;
    float* o1p = o0p + 4096;
    #pragma unroll
    for (int k = 0; k < 16; k++) {
        int j = tid + k*256;
        int o = __ldg(oinv + j);
        float2 v = unpack_f32x2(arr[o + (o >> 8)]);
        float s = __ldg(pds + j) * alphaV, bb = __ldg(bias + j);
        o0p[j] = v.x * s + bb;
        o1p[j] = v.y * s + bb;
    }
}

// ============================================================================
// Launch
// ============================================================================
extern "C" void kernel_launch(void* const* d_in, const int* in_sizes, int n_in,
                              void* d_out, int out_size)
{
    const float* x     = (const float*)d_in[0];
    const float* core  = (const float*)d_in[1];
    const float* fo0   = (const float*)d_in[2];
    const float* fo1   = (const float*)d_in[3];
    const float* fo2   = (const float*)d_in[4];
    const float* fi0   = (const float*)d_in[5];
    const float* fi1   = (const float*)d_in[6];
    const float* fi2   = (const float*)d_in[7];
    const float* bias  = (const float*)d_in[8];
    const float* alpha = (const float*)d_in[9];
    const float* pds   = (const float*)d_in[10];
    const int*   iperm = (const int*)d_in[11];
    const int*   oinv  = (const int*)d_in[12];
    float* out = (float*)d_out;

    int NT = in_sizes[0] / 4096;      // tokens (8192)
    int nPairs = NT / 2;              // 4096

    cudaFuncSetAttribute(k_input, cudaFuncAttributeMaxDynamicSharedMemorySize,
                         K1_SMEM_BYTES);
    cudaFuncSetAttribute(k_input, cudaFuncAttributePreferredSharedMemoryCarveout,
                         100);
    cudaFuncSetAttribute(k_output, cudaFuncAttributeMaxDynamicSharedMemorySize,
                         K3_SMEM_BYTES);
    cudaFuncSetAttribute(k_output, cudaFuncAttributePreferredSharedMemoryCarveout,
                         100);

    k_input<<<nPairs/2, 256, K1_SMEM_BYTES>>>(x, iperm, fi0, fi1, fi2);
    dim3 ggrid(nPairs / GP, 512 / GO);
    k_gemm<<<ggrid, 256>>>(core);
    k_output<<<nPairs, 256, K3_SMEM_BYTES>>>(fo0, fo1, fo2, bias, alpha, pds,
                                             oinv, out);
}